// round 17
// baseline (speedup 1.0000x reference)
#include <cuda_runtime.h>
#include <cstdint>

#define NNODES 8192
#define FEATD  1024
#define HDIM   512
#define GDIM   (5*HDIM)
#define NCTA   128
#define WPC    4                 // recurrence warps per CTA; warp w owns unit cta*4+w
#define NTHR   256               // 4 recurrence warps + 4 GEMM warps
#define NVC    16                // value mailbox copies (8B {val,tag})
#define SENT   0xFFC0DEADu      // sentinel for g_C only (general-tree path)

// GEMM tiling: 128(M) x 64(N) x 1024(K) tiles, row-block-major order
#define XT    40                 // xgb col-tiles per row-block (2560/64)
#define PT    8                  // pxb col-tiles per row-block (512/64)
#define TPB   (XT + PT)          // 48 tiles per row-block of 128 nodes
#define NBLK  (NNODES / 128)     // 64 row-blocks
#define NTILES (NBLK * TPB)      // 3072

// Scratch (static __device__ arrays: allocation-free per harness rules)
__device__ float g_xgb[(size_t)NNODES * GDIM];   // Wx·x + bx + bh   [N,5H]
__device__ float g_pxb[(size_t)NNODES * HDIM];   // Wpx·x + bpx      [N,H]
__device__ float g_C[(size_t)NNODES * HDIM];     // cell states      [N,H]
// Fused mailbox: [parity][copy][unit] = {h bits, tag = t+1}    (128KB)
__device__ __align__(128) uint2 g_mval[2][NVC][HDIM];
// GEMM work queue + per-row-block readiness
__device__ unsigned g_tile_ctr;
__device__ unsigned g_blk_done[NBLK];

__device__ __forceinline__ float sigm(float x) {
    return 1.0f / (1.0f + __expf(-x));
}
__device__ __forceinline__ float tanhfast(float x) {
    return 1.0f - 2.0f / (__expf(2.0f * x) + 1.0f);
}
__device__ __forceinline__ uint4 ld_volatile_u4(const void* p) {
    uint4 v;
    asm volatile("ld.volatile.global.v4.b32 {%0,%1,%2,%3}, [%4];"
                 : "=r"(v.x), "=r"(v.y), "=r"(v.z), "=r"(v.w) : "l"(p) : "memory");
    return v;
}
__device__ __forceinline__ float ld_volatile_f(const float* p) {
    float v;
    asm volatile("ld.volatile.global.f32 %0, [%1];" : "=f"(v) : "l"(p) : "memory");
    return v;
}
__device__ __forceinline__ unsigned ld_acquire_u32(const unsigned* p) {
    unsigned v;
    asm volatile("ld.acquire.gpu.global.u32 %0, [%1];" : "=r"(v) : "l"(p) : "memory");
    return v;
}
__device__ __forceinline__ void st_v2_u32(void* p, unsigned a, unsigned b) {
    asm volatile("st.global.v2.b32 [%0], {%1,%2};" :: "l"(p), "r"(a), "r"(b) : "memory");
}
__device__ __forceinline__ float desent(float v) {   // g_C values only
    return (__float_as_uint(v) == SENT) ? __uint_as_float(SENT ^ 1u) : v;
}

#define BAR1() asm volatile("bar.sync 1, 128;" ::: "memory")   // recurrence warps
#define BAR2() asm volatile("bar.sync 2, 128;" ::: "memory")   // GEMM warps

// ---------------------------------------------------------------------------
// Per-launch reset: mailbox + work counters + sentinel-poison g_C (16MB).
// ---------------------------------------------------------------------------
#define MV_U4   (int)(sizeof(g_mval) / 16)       // 8192
#define GC_F4   (NNODES * HDIM / 4)              // 1048576
__global__ void poison_kernel(float4* __restrict__ gc) {
    int i = blockIdx.x * blockDim.x + threadIdx.x;
    if (i == 0) g_tile_ctr = 0u;
    if (i < NBLK) g_blk_done[i] = 0u;
    if (i < MV_U4)
        ((uint4*)g_mval)[i] = make_uint4(0u, 0u, 0u, 0u);
    int j = i - MV_U4;
    if (j >= 0 && j < GC_F4) {
        float f = __uint_as_float(SENT);
        gc[j] = make_float4(f, f, f, f);
    }
}

// ---------------------------------------------------------------------------
// GEMM worker: warps 4..7 of every CTA (128 threads, named barrier 2).
// Drains a global tile queue in row-block-major order. Tile = 128x64x1024.
// Per-thread 8x8 accumulators; thread grid 16(ty) x 8(tx).
// On tile completion: __threadfence + atomicAdd on the row-block counter.
// ---------------------------------------------------------------------------
__device__ void gemm_worker(
    const float* __restrict__ features,
    const float* __restrict__ Wx,  const float* __restrict__ bx,
    const float* __restrict__ bh,
    const float* __restrict__ Wpx, const float* __restrict__ bpx,
    float As[8][132], float Bs[8][68], unsigned* s_tau, int gtid)
{
    const int ty = gtid >> 3;        // 0..15
    const int tx = gtid & 7;         // 0..7

    for (;;) {
        if (gtid == 0) *s_tau = atomicAdd(&g_tile_ctr, 1u);
        BAR2();
        const unsigned tau = *s_tau;
        if (tau >= NTILES) break;

        const int b = tau / TPB;
        const int r = tau % TPB;
        const float* Bmat; const float* b1; const float* b2;
        float* out; int N; int colbase;
        if (r < XT) { Bmat = Wx;  b1 = bx;  b2 = bh;     out = g_xgb;
                      N = GDIM; colbase = r * 64; }
        else        { Bmat = Wpx; b1 = bpx; b2 = nullptr; out = g_pxb;
                      N = HDIM; colbase = (r - XT) * 64; }
        const int rowbase = b * 128;

        float acc[8][8];
#pragma unroll
        for (int i = 0; i < 8; i++)
#pragma unroll
            for (int j = 0; j < 8; j++) acc[i][j] = 0.0f;

        const float* Arow = features + (size_t)(rowbase + gtid) * FEATD;
        const float* Brow = (gtid < 64)
            ? Bmat + (size_t)(colbase + gtid) * FEATD : nullptr;

        for (int k0 = 0; k0 < FEATD; k0 += 8) {
            float4 a0 = *(const float4*)(Arow + k0);
            float4 a1 = *(const float4*)(Arow + k0 + 4);
            As[0][gtid] = a0.x; As[1][gtid] = a0.y;
            As[2][gtid] = a0.z; As[3][gtid] = a0.w;
            As[4][gtid] = a1.x; As[5][gtid] = a1.y;
            As[6][gtid] = a1.z; As[7][gtid] = a1.w;
            if (gtid < 64) {
                float4 q0 = *(const float4*)(Brow + k0);
                float4 q1 = *(const float4*)(Brow + k0 + 4);
                Bs[0][gtid] = q0.x; Bs[1][gtid] = q0.y;
                Bs[2][gtid] = q0.z; Bs[3][gtid] = q0.w;
                Bs[4][gtid] = q1.x; Bs[5][gtid] = q1.y;
                Bs[6][gtid] = q1.z; Bs[7][gtid] = q1.w;
            }
            BAR2();
#pragma unroll
            for (int k = 0; k < 8; k++) {
                float ar[8], br[8];
#pragma unroll
                for (int i = 0; i < 8; i++) ar[i] = As[k][ty * 8 + i];
#pragma unroll
                for (int j = 0; j < 8; j++) br[j] = Bs[k][tx * 8 + j];
#pragma unroll
                for (int i = 0; i < 8; i++)
#pragma unroll
                    for (int j = 0; j < 8; j++)
                        acc[i][j] = fmaf(ar[i], br[j], acc[i][j]);
            }
            BAR2();
        }

        // epilogue: bias add + vectorized store
        float bv[8];
#pragma unroll
        for (int j = 0; j < 8; j++) {
            bv[j] = b1[colbase + tx * 8 + j];
            if (b2) bv[j] += b2[colbase + tx * 8 + j];
        }
#pragma unroll
        for (int i = 0; i < 8; i++) {
            float* op = out + (size_t)(rowbase + ty * 8 + i) * N
                            + colbase + tx * 8;
            *(float4*)(op)     = make_float4(acc[i][0] + bv[0], acc[i][1] + bv[1],
                                             acc[i][2] + bv[2], acc[i][3] + bv[3]);
            *(float4*)(op + 4) = make_float4(acc[i][4] + bv[4], acc[i][5] + bv[5],
                                             acc[i][6] + bv[6], acc[i][7] + bv[7]);
        }
        __threadfence();                               // data before flag
        if (gtid == 0) atomicAdd(&g_blk_done[b], 1u);
        BAR2();                                        // protect s_tau + As/Bs
    }
}

// ---------------------------------------------------------------------------
// Fused persistent kernel. 128 CTAs x 256 threads.
// Warps 0..3: R15 recurrence (16-copy fused {value,tag32} mailbox, cross-step
//   poll prefetch), with bar.sync 1,128 instead of __syncthreads, gated on
//   per-row-block xg/px readiness flags every 128 steps.
// Warps 4..7: GEMM tile team (queue-driven, row-block-major).
// ---------------------------------------------------------------------------
__global__ __launch_bounds__(NTHR, 1) void treelstm_fused_kernel(
    const float* __restrict__ Wh, const int* __restrict__ parents,
    float* __restrict__ Hout,
    const float* __restrict__ features,
    const float* __restrict__ Wx,  const float* __restrict__ bx,
    const float* __restrict__ bh,
    const float* __restrict__ Wpx, const float* __restrict__ bpx)
{
    __shared__ float    s_h[HDIM];       // assembled h[parent] (2KB)
    __shared__ int      s_par[NNODES];   // parents table (32KB)
    __shared__ float    As[8][132];      // GEMM A tile (4.2KB)
    __shared__ float    Bs[8][68];       // GEMM B tile (2.2KB)
    __shared__ unsigned s_tau;           // GEMM tile id broadcast

    const int cta  = blockIdx.x;
    const int w    = threadIdx.x >> 5;
    const int lane = threadIdx.x & 31;

    // Stage parents into SMEM (all 256 threads), then split roles.
    for (int i = threadIdx.x; i < NNODES; i += NTHR) s_par[i] = parents[i];
    __syncthreads();

    if (w >= WPC) {
        gemm_worker(features, Wx, bx, bh, Wpx, bpx, As, Bs, &s_tau,
                    threadIdx.x - 128);
        return;
    }

    // ---------------- recurrence warps (0..3) ----------------
    const int unit = cta * WPC + w;
    const int cval = cta & (NVC - 1);    // this CTA's mailbox copy (8 readers)
    const int qu   = 128 * w;            // this warp's unit quarter

    // Pin this unit's 5 Wh rows in registers: lane covers k = 4*lane + 128*c.
    float4 wv[5][4];
#pragma unroll
    for (int g = 0; g < 5; g++) {
        const float* wrow = Wh + (size_t)(g * HDIM + unit) * HDIM + 4 * lane;
#pragma unroll
        for (int c = 0; c < 4; c++)
            wv[g][c] = *(const float4*)(wrow + 128 * c);
    }

    // Wait for row-block 0 of xgb/pxb, then load node-0 static terms.
    while (ld_acquire_u32(&g_blk_done[0]) < TPB) { __nanosleep(100); }
    float xg[5], px;
#pragma unroll
    for (int g = 0; g < 5; g++) xg[g] = g_xgb[(size_t)(g * HDIM + unit)];
    px = g_pxb[unit];

    float c_last = 0.0f;
    int p = s_par[0];

    uint4 pv0, pv1;                  // cross-step prefetched poll sample
    bool  have_pf = false;

    for (int t = 0; t < NNODES; t++) {
        const int p_next = (t + 1 < NNODES) ? s_par[t + 1] : -1;

        float4 h0, h1, h2, h3;
        if (p >= 0) {
            const unsigned e = (unsigned)(p + 1);
            const uint2* mp = &g_mval[p & 1][cval][qu + 2 * lane];
            // --- fused detect+load, seeded by the cross-step prefetch ---
            {
                uint4 v0, v1;
                if (have_pf) { v0 = pv0; v1 = pv1; }
                else         { v0 = ld_volatile_u4(mp);
                               v1 = ld_volatile_u4(mp + 64); }
                for (;;) {
                    bool ok = (v0.y == e) & (v0.w == e) &
                              (v1.y == e) & (v1.w == e);
                    if (__all_sync(0xffffffffu, ok)) break;
                    v0 = ld_volatile_u4(mp);
                    v1 = ld_volatile_u4(mp + 64);
                }
                *(float2*)&s_h[qu + 2 * lane] =
                    make_float2(__uint_as_float(v0.x), __uint_as_float(v0.z));
                *(float2*)&s_h[qu + 64 + 2 * lane] =
                    make_float2(__uint_as_float(v1.x), __uint_as_float(v1.z));
            }
            BAR1();                            // s_h fully assembled
            h0 = *(const float4*)&s_h[4 * lane +   0];
            h1 = *(const float4*)&s_h[4 * lane + 128];
            h2 = *(const float4*)&s_h[4 * lane + 256];
            h3 = *(const float4*)&s_h[4 * lane + 384];
        } else {
            h0 = h1 = h2 = h3 = make_float4(0.f, 0.f, 0.f, 0.f);
        }

        // --- 5 dot products (this unit's i,o,f,u,r rows) ---
        float acc[5];
#pragma unroll
        for (int g = 0; g < 5; g++) {
            float a0 = fmaf(wv[g][0].x, h0.x, fmaf(wv[g][0].y, h0.y,
                       fmaf(wv[g][0].z, h0.z, wv[g][0].w * h0.w)));
            float a1 = fmaf(wv[g][1].x, h1.x, fmaf(wv[g][1].y, h1.y,
                       fmaf(wv[g][1].z, h1.z, wv[g][1].w * h1.w)));
            float a2 = fmaf(wv[g][2].x, h2.x, fmaf(wv[g][2].y, h2.y,
                       fmaf(wv[g][2].z, h2.z, wv[g][2].w * h2.w)));
            float a3 = fmaf(wv[g][3].x, h3.x, fmaf(wv[g][3].y, h3.y,
                       fmaf(wv[g][3].z, h3.z, wv[g][3].w * h3.w)));
            acc[g] = (a0 + a1) + (a2 + a3);
        }

        // --- fused 5-way butterfly reduce: ALL lanes end with the sums ---
#pragma unroll
        for (int off = 16; off; off >>= 1) {
#pragma unroll
            for (int g = 0; g < 5; g++)
                acc[g] += __shfl_xor_sync(0xffffffffu, acc[g], off);
        }

        // --- gate math on ALL lanes (redundant; enables wide fan-out) ---
        float cpar = 0.0f;
        if (p >= 0) {
            if (p == t - 1) {
                cpar = c_last;                           // chain fast path
            } else {
                const float* cp = &g_C[(size_t)p * HDIM + unit];
                do { cpar = ld_volatile_f(cp); }         // general tree
                while (__float_as_uint(cpar) == SENT);
            }
        }
        float iv = sigm(acc[0] + xg[0]);
        float ov = sigm(acc[1] + xg[1]);
        float fv = sigm(acc[2] + xg[2]);
        float uv = tanhfast(acc[3] + xg[3]);
        float rv = sigm(acc[4] + xg[4]);
        float c  = desent(fmaf(fv, cpar, iv * uv));
        float hh = ov * tanhfast(c);
        float hf = rv * hh + (1.0f - rv) * px;
        c_last = c;

        // --- publish: lanes 16..31 fan {hf, t+1} out to the 16 copies ---
        const unsigned tagp = (unsigned)(t + 1);
        if (lane >= 16)
            st_v2_u32(&g_mval[t & 1][lane - 16][unit],
                      __float_as_uint(hf), tagp);
        if (lane == 0) Hout[(size_t)t * HDIM + unit] = hf;  // final output
        if (lane == 1) g_C[(size_t)t * HDIM + unit]  = c;   // general-tree state

        // --- cross-step poll prefetch (R15 placement: right after publish) ---
        if (p_next >= 0) {
            const uint2* mpn = &g_mval[p_next & 1][cval][qu + 2 * lane];
            pv0 = ld_volatile_u4(mpn);
            pv1 = ld_volatile_u4(mpn + 64);
            have_pf = true;
        } else {
            have_pf = false;
        }

        // --- static prefetch, gated on row-block readiness every 128 steps ---
        if (t + 1 < NNODES) {
            if (((t + 1) & 127) == 0) {
                const unsigned* bf = &g_blk_done[(t + 1) >> 7];
                while (ld_acquire_u32(bf) < TPB) { __nanosleep(100); }
            }
#pragma unroll
            for (int g = 0; g < 5; g++)
                xg[g] = g_xgb[(size_t)(t + 1) * GDIM + g * HDIM + unit];
            px = g_pxb[(size_t)(t + 1) * HDIM + unit];
        }

        // s_h reuse is globally gated on the chain; bar only for non-chain t+1.
        if (t + 1 < NNODES && p_next != t) BAR1();

        p = p_next;
    }
}

extern "C" void kernel_launch(void* const* d_in, const int* in_sizes, int n_in,
                              void* d_out, int out_size) {
    const float* features = (const float*)d_in[0];
    const int*   parents  = (const int*)d_in[1];
    const float* Wpx      = (const float*)d_in[2];
    const float* bpx      = (const float*)d_in[3];
    const float* Wx       = (const float*)d_in[4];
    const float* bx       = (const float*)d_in[5];
    const float* Wh       = (const float*)d_in[6];
    const float* bh       = (const float*)d_in[7];
    float* Hout = (float*)d_out;

    float* d_C = nullptr;
    cudaGetSymbolAddress((void**)&d_C, g_C);

    // 1) reset mailbox + work counters, sentinel-poison g_C (replay-safe)
    poison_kernel<<<(MV_U4 + GC_F4 + 255) / 256, 256>>>((float4*)d_C);

    // 2) fused kernel: recurrence warps + in-kernel GEMM team (overlapped)
    treelstm_fused_kernel<<<NCTA, NTHR>>>(Wh, parents, Hout,
                                          features, Wx, bx, bh, Wpx, bpx);
}